// round 13
// baseline (speedup 1.0000x reference)
#include <cuda_runtime.h>
#include <math.h>

#define NH  16
#define HD  64
#define KC  16
#define F4  256
#define BB  4
#define LL  2048
#define CC  1024
#define NCH 128
#define EPSF 1e-6f

// ---------------- scratch (static device globals; no allocation) ----------------
__device__ float g_XQ[BB*NH*LL*HD];   // [b][h][l][d]
__device__ float g_XK[BB*NH*LL*HD];
__device__ float g_XV[BB*NH*LL*HD];
__device__ float g_lr[BB*NH*LL];      // sigmoid lr per (b,h,l)
__device__ float g_XQW[BB*LL*CC];     // scan output -> post-LN in place

// ---------------- math ----------------
__device__ __forceinline__ float ftanh(float x) {
    float a = fminf(fmaxf(2.f * x, -60.f), 60.f);
    float e = __expf(a);
    return (e - 1.f) / (e + 1.f);
}
__device__ __forceinline__ float gelu_f(float x) {
    return 0.5f * x * (1.f + ftanh(0.79788456f * x * (1.f + 0.044715f * x * x)));
}
__device__ __forceinline__ float gelu_b(float x) {
    float t = ftanh(0.79788456f * x * (1.f + 0.044715f * x * x));
    return 0.5f * x * ((1.f - t * t) * (0.79788456f + 0.1070322243f * x * x)) + 0.5f * (1.f + t);
}

// ---------------- NT SGEMM: C[m,n] = sum_k A[m,k]*Bw[n,k]; M=8192,N=1024,K=1024 ----------------
// MODE 0: A = arg, scatter to g_XQ/g_XK/g_XV.
// MODE 1: A = g_XQW (device symbol, resolved IN DEVICE CODE), row-major Co.
template<int MODE>
__global__ __launch_bounds__(256, 2) void sgemm_nt(const float* __restrict__ Aarg,
                                                   const float* __restrict__ Bw,
                                                   float* __restrict__ Co, int sel)
{
    // CRITICAL: device-symbol operand must be resolved here, not passed from host
    // (host-side shadow address silently reads zeros over GB300 ATS).
    const float* A = (MODE == 1) ? (const float*)g_XQW : Aarg;

    __shared__ float As[2][16][132];
    __shared__ float Bs[2][16][132];
    int t = threadIdx.x;
    int m0 = blockIdx.y * 128, n0 = blockIdx.x * 128;
    int lr_ = t >> 2, lc = (t & 3) * 4;
    int tx = t & 15, ty = t >> 4;

    const float4* Ag0 = (const float4*)(A  + (size_t)(m0 + lr_)      * 1024 + lc);
    const float4* Ag1 = (const float4*)(A  + (size_t)(m0 + lr_ + 64) * 1024 + lc);
    const float4* Bg0 = (const float4*)(Bw + (size_t)(n0 + lr_)      * 1024 + lc);
    const float4* Bg1 = (const float4*)(Bw + (size_t)(n0 + lr_ + 64) * 1024 + lc);

    float4 pa0 = Ag0[0], pa1 = Ag1[0], pb0 = Bg0[0], pb1 = Bg1[0];
    int buf = 0;
    {
        const float *a = (const float*)&pa0, *a2 = (const float*)&pa1;
        const float *bb = (const float*)&pb0, *b2 = (const float*)&pb1;
        #pragma unroll
        for (int kk = 0; kk < 4; kk++) {
            As[buf][lc+kk][lr_] = a[kk];  As[buf][lc+kk][lr_+64] = a2[kk];
            Bs[buf][lc+kk][lr_] = bb[kk]; Bs[buf][lc+kk][lr_+64] = b2[kk];
        }
    }
    __syncthreads();

    float acc[8][8];
    #pragma unroll
    for (int i = 0; i < 8; i++)
        #pragma unroll
        for (int j = 0; j < 8; j++) acc[i][j] = 0.f;

    for (int kt = 1; kt <= 64; kt++) {
        if (kt < 64) { pa0 = Ag0[kt*4]; pa1 = Ag1[kt*4]; pb0 = Bg0[kt*4]; pb1 = Bg1[kt*4]; }
        #pragma unroll
        for (int k = 0; k < 16; k++) {
            float4 a0 = *(const float4*)&As[buf][k][ty*4];
            float4 a1 = *(const float4*)&As[buf][k][ty*4+64];
            float4 b0 = *(const float4*)&Bs[buf][k][tx*4];
            float4 b1 = *(const float4*)&Bs[buf][k][tx*4+64];
            float av[8] = {a0.x,a0.y,a0.z,a0.w,a1.x,a1.y,a1.z,a1.w};
            float bv[8] = {b0.x,b0.y,b0.z,b0.w,b1.x,b1.y,b1.z,b1.w};
            #pragma unroll
            for (int i = 0; i < 8; i++)
                #pragma unroll
                for (int j = 0; j < 8; j++) acc[i][j] += av[i] * bv[j];
        }
        if (kt < 64) {
            buf ^= 1;
            const float *a = (const float*)&pa0, *a2 = (const float*)&pa1;
            const float *bb = (const float*)&pb0, *b2 = (const float*)&pb1;
            #pragma unroll
            for (int kk = 0; kk < 4; kk++) {
                As[buf][lc+kk][lr_] = a[kk];  As[buf][lc+kk][lr_+64] = a2[kk];
                Bs[buf][lc+kk][lr_] = bb[kk]; Bs[buf][lc+kk][lr_+64] = b2[kk];
            }
            __syncthreads();
        }
    }

    #pragma unroll
    for (int ri = 0; ri < 8; ri++) {
        int m = m0 + ty*4 + (ri & 3) + (ri >> 2) * 64;
        #pragma unroll
        for (int cj = 0; cj < 2; cj++) {
            int n = n0 + tx*4 + cj*64;
            float4 v = make_float4(acc[ri][cj*4], acc[ri][cj*4+1], acc[ri][cj*4+2], acc[ri][cj*4+3]);
            if (MODE == 0) {
                int b = m >> 11, l = m & 2047, hh = n >> 6, d = n & 63;
                float* dst = (sel == 0) ? g_XQ : (sel == 1) ? g_XK : g_XV;
                *(float4*)&dst[((size_t)((b << 4) + hh) << 17) + (l << 6) + d] = v;
            } else {
                *(float4*)&Co[(size_t)m * 1024 + n] = v;
            }
        }
    }
}

// ---------------- RoPE: adjacent-pair rotation ----------------
__global__ __launch_bounds__(256) void rope_kernel()
{
    int p = blockIdx.x * 256 + threadIdx.x;
    int d2 = p & 31;
    int l  = (p >> 5) & 2047;
    int bh = p >> 16;
    size_t base = ((size_t)bh << 17) + ((size_t)l << 6) + 2 * d2;
    float inv = __expf(-(float)d2 * (9.21034037f / 32.f));
    float s, c;
    sincosf((float)(l & 15) * inv, &s, &c);
    float2 q = *(float2*)&g_XQ[base];
    float2 k = *(float2*)&g_XK[base];
    *(float2*)&g_XQ[base] = make_float2(q.x * c - q.y * s, q.y * c + q.x * s);
    *(float2*)&g_XK[base] = make_float2(k.x * c - k.y * s, k.y * c + k.x * s);
}

// ---------------- lr sigmoid ----------------
__global__ __launch_bounds__(256) void lr_kernel(const float* __restrict__ hs,
                                                 const float* __restrict__ lrw,
                                                 const float* __restrict__ lrb)
{
    __shared__ float row[1024];
    int bl = blockIdx.x, t = threadIdx.x;
    *(float4*)&row[t * 4] = *(const float4*)&hs[(size_t)bl * 1024 + t * 4];
    __syncthreads();
    int w = t >> 5, lane = t & 31;
    for (int hh = w; hh < 16; hh += 8) {
        float s = 0.f;
        const float* wv = lrw + hh * 1024;
        for (int c = lane; c < 1024; c += 32) s += row[c] * wv[c];
        #pragma unroll
        for (int o = 16; o; o >>= 1) s += __shfl_xor_sync(0xffffffffu, s, o);
        if (lane == 0)
            g_lr[(size_t)((bl >> 11) * 16 + hh) * 2048 + (bl & 2047)] =
                1.f / (1.f + __expf(-(s + lrb[hh])));
    }
}

// ---------------- post-LN in place ----------------
__global__ __launch_bounds__(256) void postln_kernel(const float* __restrict__ pw,
                                                     const float* __restrict__ pb)
{
    __shared__ float red[256];
    int m = blockIdx.x, t = threadIdx.x;
    float4 x = *(float4*)&g_XQW[(size_t)m * 1024 + t * 4];
    red[t] = x.x + x.y + x.z + x.w;
    __syncthreads();
    #pragma unroll
    for (int o = 128; o; o >>= 1) { if (t < o) red[t] += red[t + o]; __syncthreads(); }
    float mu = red[0] * (1.f / 1024.f);
    __syncthreads();
    float dx = x.x - mu, dy = x.y - mu, dz = x.z - mu, dw = x.w - mu;
    red[t] = dx*dx + dy*dy + dz*dz + dw*dw;
    __syncthreads();
    #pragma unroll
    for (int o = 128; o; o >>= 1) { if (t < o) red[t] += red[t + o]; __syncthreads(); }
    float rstd = rsqrtf(red[0] * (1.f / 1024.f) + EPSF);
    float4 w = *(const float4*)&pw[t * 4];
    float4 b = *(const float4*)&pb[t * 4];
    *(float4*)&g_XQW[(size_t)m * 1024 + t * 4] =
        make_float4(w.x*dx*rstd + b.x, w.y*dy*rstd + b.y, w.z*dz*rstd + b.z, w.w*dw*rstd + b.w);
}

// ---------------- TTT scan: one CTA per (b,h), state in SMEM ----------------
#define SCAN_SMEM_BYTES (56016 * 4)

__global__ __launch_bounds__(256, 1) void scan_kernel(
    const float* __restrict__ lt_idx,
    const float* __restrict__ lnw_g, const float* __restrict__ lnb_g,
    const float* __restrict__ W1g,   const float* __restrict__ b1g,
    const float* __restrict__ W2g,   const float* __restrict__ b2g)
{
    extern __shared__ float sm[];
    float* sW1  = sm;            // [64][256]   (row d, col f)
    float* sW2  = sm + 16384;    // [256][65]   (row f, col j; padded)
    float* sb1  = sm + 33024;    // [256]
    float* sb2  = sm + 33280;    // [64]
    float* sxq  = sm + 33344;    // [16][68]
    float* sxk  = sm + 34432;    // [16][68]
    float* sxv  = sm + 35520;    // [16][68]
    float* sZ1  = sm + 36608;    // [16][256]
    float* sX2  = sm + 40704;    // [16][260]
    float* sX2b = sm + 44864;    // [16][260]
    float* sG1  = sm + 49024;    // [16][256]
    float* sG2  = sm + 53120;    // [16][68]
    float* sZ2  = sm + 54208;    // [16][68]
    float* sA1  = sm + 55296;    // [16][17]
    float* sA2  = sm + 55568;    // [16][17]
    float* slnw = sm + 55840;    // [64]
    float* slnb = sm + 55904;    // [64]
    float* slrh = sm + 55968;    // [16]
    float* stok = sm + 55984;    // [16]
    float* slast= sm + 56000;    // [16]

    int t = threadIdx.x;
    int bh = blockIdx.x;
    int b = bh >> 4, h = bh & 15;

    // load state
    {
        const float* w1 = W1g + h * 16384;          // [HD][F4] row-major
        for (int i = t * 4; i < 16384; i += 1024)
            *(float4*)&sW1[i] = *(const float4*)&w1[i];
        const float* w2 = W2g + h * 16384 + t * 64; // row f = t
        #pragma unroll
        for (int j = 0; j < 64; j += 4) {
            float4 v = *(const float4*)&w2[j];
            sW2[t*65+j] = v.x; sW2[t*65+j+1] = v.y; sW2[t*65+j+2] = v.z; sW2[t*65+j+3] = v.w;
        }
        sb1[t] = b1g[h * 256 + t];
        if (t < 64) { sb2[t] = b2g[h*64+t]; slnw[t] = lnw_g[h*64+t]; slnb[t] = lnb_g[h*64+t]; }
        if (t < 16) stok[t] = fmaxf(1.f / (float)(t + 1) + lt_idx[t], 0.f);
    }
    __syncthreads();

    const size_t xbase = (size_t)bh << 17;

    for (int n = 0; n < NCH; n++) {
        int l0 = n * 16;
        // load chunk
        {
            int r = t >> 4, c = (t & 15) * 4;
            size_t g = xbase + (size_t)(l0 + r) * 64 + c;
            *(float4*)&sxq[r*68 + c] = *(const float4*)&g_XQ[g];
            *(float4*)&sxk[r*68 + c] = *(const float4*)&g_XK[g];
            *(float4*)&sxv[r*68 + c] = *(const float4*)&g_XV[g];
        }
        if (t < 16) {
            slrh[t] = (1.f / 64.f) * g_lr[(size_t)bh * LL + l0 + t];
        }
        __syncthreads();
        if (t < 16) slast[t] = stok[15] * slrh[t];

        // Z1 = xk@W1 + b1 ; X2 = gelu(Z1)    (thread = column f)
        {
            float acc[16];
            float bf = sb1[t];
            #pragma unroll
            for (int i = 0; i < 16; i++) acc[i] = bf;
            for (int d = 0; d < 64; d += 4) {
                float w0 = sW1[(d+0)*256+t], w1 = sW1[(d+1)*256+t];
                float w2 = sW1[(d+2)*256+t], w3 = sW1[(d+3)*256+t];
                #pragma unroll
                for (int i = 0; i < 16; i++) {
                    float4 x4 = *(float4*)&sxk[i*68 + d];
                    acc[i] += x4.x*w0 + x4.y*w1 + x4.z*w2 + x4.w*w3;
                }
            }
            #pragma unroll
            for (int i = 0; i < 16; i++) { sZ1[i*256+t] = acc[i]; sX2[i*260+t] = gelu_f(acc[i]); }
        }
        __syncthreads();

        // Z2 = X2@W2 + b2  (64 cols x 4 rows per thread) ; A1 coefs
        {
            int jj = t & 63, i0 = (t >> 6) * 4;
            float z[4];
            float bz = sb2[jj];
            z[0] = z[1] = z[2] = z[3] = bz;
            for (int f = 0; f < 256; f += 4) {
                float w0 = sW2[(f+0)*65+jj], w1 = sW2[(f+1)*65+jj];
                float w2 = sW2[(f+2)*65+jj], w3 = sW2[(f+3)*65+jj];
                #pragma unroll
                for (int k = 0; k < 4; k++) {
                    float4 x4 = *(float4*)&sX2[(i0+k)*260 + f];
                    z[k] += x4.x*w0 + x4.y*w1 + x4.z*w2 + x4.w*w3;
                }
            }
            #pragma unroll
            for (int k = 0; k < 4; k++) sZ2[(i0+k)*68 + jj] = z[k];

            int ia = t & 15, ja = t >> 4;
            float dot = 0.f;
            for (int d = 0; d < 64; d += 4) {
                float4 q4 = *(float4*)&sxq[ia*68 + d];
                float4 k4 = *(float4*)&sxk[ja*68 + d];
                dot += q4.x*k4.x + q4.y*k4.y + q4.z*k4.z + q4.w*k4.w;
            }
            sA1[ia*17+ja] = (ja <= ia) ? stok[ia] * slrh[ja] * (dot + 1.f) : 0.f;
        }
        __syncthreads();

        // gZ2 = ln_fused_l2_bwd(Z2, xv - xk)   (warp per 2 rows)
        {
            int w = t >> 5, lane = t & 31;
            #pragma unroll
            for (int rr = 0; rr < 2; rr++) {
                int i = w * 2 + rr;
                float z0 = sZ2[i*68+lane], z1 = sZ2[i*68+lane+32];
                float s = z0 + z1;
                #pragma unroll
                for (int o = 16; o; o >>= 1) s += __shfl_xor_sync(0xffffffffu, s, o);
                float mu = s * (1.f / 64.f);
                float d0 = z0 - mu, d1 = z1 - mu;
                float v = d0*d0 + d1*d1;
                #pragma unroll
                for (int o = 16; o; o >>= 1) v += __shfl_xor_sync(0xffffffffu, v, o);
                float rstd = rsqrtf(v * (1.f / 64.f) + EPSF);
                float xh0 = d0*rstd, xh1 = d1*rstd;
                float g0 = slnw[lane], g1 = slnw[lane+32];
                float tg0 = sxv[i*68+lane]    - sxk[i*68+lane];
                float tg1 = sxv[i*68+lane+32] - sxk[i*68+lane+32];
                float go0 = (g0*xh0 + slnb[lane]    - tg0) * g0;
                float go1 = (g1*xh1 + slnb[lane+32] - tg1) * g1;
                float s1 = go0 + go1, s2 = go0*xh0 + go1*xh1;
                #pragma unroll
                for (int o = 16; o; o >>= 1) {
                    s1 += __shfl_xor_sync(0xffffffffu, s1, o);
                    s2 += __shfl_xor_sync(0xffffffffu, s2, o);
                }
                float inv = rstd * (1.f / 64.f);
                sG2[i*68+lane]    = (64.f*go0 - s1 - xh0*s2) * inv;
                sG2[i*68+lane+32] = (64.f*go1 - s1 - xh1*s2) * inv;
            }
        }
        __syncthreads();

        // gZ1 = (gZ2 @ W2^T) * gelu'(Z1)   (thread = column f)
        {
            float acc[16];
            #pragma unroll
            for (int i = 0; i < 16; i++) acc[i] = 0.f;
            for (int j = 0; j < 64; j += 4) {
                float w0 = sW2[t*65+j],   w1 = sW2[t*65+j+1];
                float w2 = sW2[t*65+j+2], w3 = sW2[t*65+j+3];
                #pragma unroll
                for (int i = 0; i < 16; i++) {
                    float4 g4 = *(float4*)&sG2[i*68 + j];
                    acc[i] += g4.x*w0 + g4.y*w1 + g4.z*w2 + g4.w*w3;
                }
            }
            #pragma unroll
            for (int i = 0; i < 16; i++) sG1[i*256+t] = acc[i] * gelu_b(sZ1[i*256+t]);
        }
        __syncthreads();

        // Z1_bar = xq@W1 + b1 - A1 @ gZ1 ; X2b = gelu
        {
            float acc[16];
            float bf = sb1[t];
            #pragma unroll
            for (int i = 0; i < 16; i++) acc[i] = bf;
            for (int d = 0; d < 64; d += 4) {
                float w0 = sW1[(d+0)*256+t], w1 = sW1[(d+1)*256+t];
                float w2 = sW1[(d+2)*256+t], w3 = sW1[(d+3)*256+t];
                #pragma unroll
                for (int i = 0; i < 16; i++) {
                    float4 q4 = *(float4*)&sxq[i*68 + d];
                    acc[i] += q4.x*w0 + q4.y*w1 + q4.z*w2 + q4.w*w3;
                }
            }
            #pragma unroll
            for (int j = 0; j < 16; j++) {
                float g = sG1[j*256+t];
                #pragma unroll
                for (int i = j; i < 16; i++) acc[i] -= sA1[i*17+j] * g;
            }
            #pragma unroll
            for (int i = 0; i < 16; i++) sX2b[i*260+t] = gelu_f(acc[i]);
        }
        __syncthreads();

        // A2 coefs
        {
            int ia = t & 15, ja = t >> 4;
            float dot = 0.f;
            for (int f = 0; f < 256; f += 4) {
                float4 a4 = *(float4*)&sX2b[ia*260 + f];
                float4 b4 = *(float4*)&sX2[ja*260 + f];
                dot += a4.x*b4.x + a4.y*b4.y + a4.z*b4.z + a4.w*b4.w;
            }
            sA2[ia*17+ja] = (ja <= ia) ? stok[ia] * slrh[ja] * (dot + 1.f) : 0.f;
        }
        __syncthreads();

        // Z2_bar = X2b@W2 + b2 - A2 @ gZ2   (overwrite sZ2)
        {
            int jj = t & 63, i0 = (t >> 6) * 4;
            float z[4];
            float bz = sb2[jj];
            z[0] = z[1] = z[2] = z[3] = bz;
            for (int f = 0; f < 256; f += 4) {
                float w0 = sW2[(f+0)*65+jj], w1 = sW2[(f+1)*65+jj];
                float w2 = sW2[(f+2)*65+jj], w3 = sW2[(f+3)*65+jj];
                #pragma unroll
                for (int k = 0; k < 4; k++) {
                    float4 x4 = *(float4*)&sX2b[(i0+k)*260 + f];
                    z[k] += x4.x*w0 + x4.y*w1 + x4.z*w2 + x4.w*w3;
                }
            }
            #pragma unroll
            for (int j = 0; j < 16; j++) {
                float g = sG2[j*68 + jj];
                #pragma unroll
                for (int k = 0; k < 4; k++)
                    if (j <= i0 + k) z[k] -= sA2[(i0+k)*17+j] * g;
            }
            #pragma unroll
            for (int k = 0; k < 4; k++) sZ2[(i0+k)*68 + jj] = z[k];
        }
        __syncthreads();

        // output: xq + ln_fwd(Z2_bar)   (warp per 2 rows)
        {
            int w = t >> 5, lane = t & 31;
            #pragma unroll
            for (int rr = 0; rr < 2; rr++) {
                int i = w * 2 + rr;
                float z0 = sZ2[i*68+lane], z1 = sZ2[i*68+lane+32];
                float s = z0 + z1;
                #pragma unroll
                for (int o = 16; o; o >>= 1) s += __shfl_xor_sync(0xffffffffu, s, o);
                float mu = s * (1.f / 64.f);
                float d0 = z0 - mu, d1 = z1 - mu;
                float v = d0*d0 + d1*d1;
                #pragma unroll
                for (int o = 16; o; o >>= 1) v += __shfl_xor_sync(0xffffffffu, v, o);
                float rstd = rsqrtf(v * (1.f / 64.f) + EPSF);
                size_t orow = (size_t)(b * 2048 + l0 + i) * 1024 + h * 64;
                g_XQW[orow + lane]      = sxq[i*68+lane]    + slnw[lane]*d0*rstd    + slnb[lane];
                g_XQW[orow + lane + 32] = sxq[i*68+lane+32] + slnw[lane+32]*d1*rstd + slnb[lane+32];
            }
        }
        __syncthreads();

        // phase A: W1/b1 update (gZ1 scaled in-register) + scale sG2 in place
        {
            float g1s[16];
            #pragma unroll
            for (int j = 0; j < 16; j++) g1s[j] = sG1[j*256+t] * slast[j];
            float bs = 0.f;
            #pragma unroll
            for (int j = 0; j < 16; j++) bs += g1s[j];
            sb1[t] -= bs;
            #pragma unroll
            for (int d0 = 0; d0 < 64; d0 += 4) {
                float a0 = 0.f, a1 = 0.f, a2 = 0.f, a3 = 0.f;
                #pragma unroll
                for (int j = 0; j < 16; j++) {
                    float4 xk4 = *(float4*)&sxk[j*68 + d0];
                    a0 += xk4.x * g1s[j]; a1 += xk4.y * g1s[j];
                    a2 += xk4.z * g1s[j]; a3 += xk4.w * g1s[j];
                }
                sW1[(d0+0)*256+t] -= a0; sW1[(d0+1)*256+t] -= a1;
                sW1[(d0+2)*256+t] -= a2; sW1[(d0+3)*256+t] -= a3;
            }
            for (int idx = t; idx < 1024; idx += 256) {
                int j = idx >> 6, d = idx & 63;
                sG2[j*68 + d] *= slast[j];
            }
        }
        __syncthreads();

        // phase B: W2/b2 update (thread = row f)
        {
            float x2s[16];
            #pragma unroll
            for (int j = 0; j < 16; j++) x2s[j] = sX2[j*260+t];
            #pragma unroll
            for (int jd = 0; jd < 64; jd += 4) {
                float a0 = 0.f, a1 = 0.f, a2 = 0.f, a3 = 0.f;
                #pragma unroll
                for (int j = 0; j < 16; j++) {
                    float4 g4 = *(float4*)&sG2[j*68 + jd];
                    a0 += g4.x * x2s[j]; a1 += g4.y * x2s[j];
                    a2 += g4.z * x2s[j]; a3 += g4.w * x2s[j];
                }
                sW2[t*65+jd]   -= a0; sW2[t*65+jd+1] -= a1;
                sW2[t*65+jd+2] -= a2; sW2[t*65+jd+3] -= a3;
            }
            if (t < 64) {
                float s = 0.f;
                #pragma unroll
                for (int j = 0; j < 16; j++) s += sG2[j*68 + t];
                sb2[t] -= s;
            }
        }
        __syncthreads();
    }
}

// ---------------- launch ----------------
extern "C" void kernel_launch(void* const* d_in, const int* in_sizes, int n_in,
                              void* d_out, int out_size)
{
    const float* hs   = (const float*)d_in[0];
    const float* wq   = (const float*)d_in[1];
    const float* wk   = (const float*)d_in[2];
    const float* wv   = (const float*)d_in[3];
    const float* wo   = (const float*)d_in[4];
    const float* lti  = (const float*)d_in[5];
    const float* lrw  = (const float*)d_in[6];
    const float* lrb  = (const float*)d_in[7];
    const float* lnw  = (const float*)d_in[8];
    const float* lnb  = (const float*)d_in[9];
    const float* pw   = (const float*)d_in[10];
    const float* pb   = (const float*)d_in[11];
    const float* W1   = (const float*)d_in[12];
    const float* b1   = (const float*)d_in[13];
    const float* W2   = (const float*)d_in[14];
    const float* b2   = (const float*)d_in[15];
    float* out = (float*)d_out;

    // Idempotent, not a stream op -> graph-capture safe; no static guard (rule).
    cudaFuncSetAttribute(scan_kernel, cudaFuncAttributeMaxDynamicSharedMemorySize,
                         SCAN_SMEM_BYTES);

    dim3 gg(8, 64), bt(256);
    sgemm_nt<0><<<gg, bt>>>(hs, wq, nullptr, 0);
    sgemm_nt<0><<<gg, bt>>>(hs, wk, nullptr, 1);
    sgemm_nt<0><<<gg, bt>>>(hs, wv, nullptr, 2);
    rope_kernel<<<16384, 256>>>();
    lr_kernel<<<8192, 256>>>(hs, lrw, lrb);
    scan_kernel<<<64, 256, SCAN_SMEM_BYTES>>>(lti, lnw, lnb, W1, b1, W2, b2);
    postln_kernel<<<8192, 256>>>(pw, pb);
    sgemm_nt<1><<<gg, bt>>>(nullptr, wo, out, 0);   // A = g_XQW resolved in device code
}

// round 14
// speedup vs baseline: 1.1378x; 1.1378x over previous
#include <cuda_runtime.h>
#include <cuda_bf16.h>
#include <math.h>

#define NH  16
#define HD  64
#define KC  16
#define F4  256
#define BB  4
#define LL  2048
#define CC  1024
#define NCH 128
#define EPSF 1e-6f

// ---------------- scratch (static device globals; no allocation) ----------------
__device__ float g_XQ[BB*NH*LL*HD];   // [b][h][l][d]
__device__ float g_XK[BB*NH*LL*HD];
__device__ float g_XV[BB*NH*LL*HD];
__device__ float g_lr[BB*NH*LL];      // sigmoid lr per (b,h,l)
__device__ float g_XQW[BB*LL*CC];     // scan output -> post-LN in place

// bf16 hi/lo split scratch for tensor-core GEMMs
__device__ __nv_bfloat16 g_hs_h[BB*LL*CC], g_hs_l[BB*LL*CC];
__device__ __nv_bfloat16 g_w_h[4*CC*CC],   g_w_l[4*CC*CC];
__device__ __nv_bfloat16 g_xw_h[BB*LL*CC], g_xw_l[BB*LL*CC];

// ---------------- math ----------------
__device__ __forceinline__ float ftanh(float x) {
    float a = fminf(fmaxf(2.f * x, -60.f), 60.f);
    float e = __expf(a);
    return (e - 1.f) / (e + 1.f);
}
__device__ __forceinline__ float gelu_f(float x) {
    return 0.5f * x * (1.f + ftanh(0.79788456f * x * (1.f + 0.044715f * x * x)));
}
__device__ __forceinline__ float gelu_b(float x) {
    float t = ftanh(0.79788456f * x * (1.f + 0.044715f * x * x));
    return 0.5f * x * ((1.f - t * t) * (0.79788456f + 0.1070322243f * x * x)) + 0.5f * (1.f + t);
}

// ---------------- fp32 -> bf16 hi/lo split ----------------
__global__ __launch_bounds__(256) void cvt_kernel(const float* __restrict__ src_in,
                                                  int dst_sel, size_t dst_off, int n4)
{
    int i = blockIdx.x * 256 + threadIdx.x;
    if (i >= n4) return;
    const float* src = (dst_sel == 2) ? (const float*)g_XQW : src_in;
    __nv_bfloat16 *H, *L;
    if (dst_sel == 0)      { H = g_hs_h; L = g_hs_l; }
    else if (dst_sel == 1) { H = g_w_h;  L = g_w_l;  }
    else                   { H = g_xw_h; L = g_xw_l; }
    H += dst_off; L += dst_off;
    float4 v = ((const float4*)src)[i];
    __nv_bfloat16 h[4], l[4];
    h[0] = __float2bfloat16(v.x); l[0] = __float2bfloat16(v.x - __bfloat162float(h[0]));
    h[1] = __float2bfloat16(v.y); l[1] = __float2bfloat16(v.y - __bfloat162float(h[1]));
    h[2] = __float2bfloat16(v.z); l[2] = __float2bfloat16(v.z - __bfloat162float(h[2]));
    h[3] = __float2bfloat16(v.w); l[3] = __float2bfloat16(v.w - __bfloat162float(h[3]));
    *(uint2*)&H[(size_t)i * 4] = *(uint2*)h;
    *(uint2*)&L[(size_t)i * 4] = *(uint2*)l;
}

// ---------------- bf16 3-product tensor-core NT GEMM ----------------
// C[m,n] = sum_k A[m,k]*Bw[n,k]; M=8192,N=1024,K=1024.
// MODE 0: A = hs split, scatter into g_XQ/g_XK/g_XV (sel 0/1/2). B = weights[sel].
// MODE 1: A = XQW split, B = weights[3], write row-major Co.
#define GU (128*12)   // u32 per matrix per buffer (row stride 12 u32, conflict-free)
#define BG_SMEM (8*GU*4)

#define CP16(saddr, gptr) \
    asm volatile("cp.async.cg.shared.global [%0], [%1], 16;" :: "r"(saddr), "l"(gptr))

#define MMA_BF16(cc, aa, b0, b1) \
    asm volatile("mma.sync.aligned.m16n8k16.row.col.f32.bf16.bf16.f32 " \
        "{%0,%1,%2,%3}, {%4,%5,%6,%7}, {%8,%9}, {%0,%1,%2,%3};" \
        : "+f"(cc[0]), "+f"(cc[1]), "+f"(cc[2]), "+f"(cc[3]) \
        : "r"(aa[0]), "r"(aa[1]), "r"(aa[2]), "r"(aa[3]), "r"(b0), "r"(b1))

template<int MODE>
__global__ __launch_bounds__(256, 2) void bgemm_nt(int sel, float* __restrict__ Co)
{
    // device symbols resolved IN DEVICE CODE (GB300 ATS silently reads host shadows)
    const __nv_bfloat16* Ah = (MODE == 0) ? g_hs_h : g_xw_h;
    const __nv_bfloat16* Al = (MODE == 0) ? g_hs_l : g_xw_l;
    const __nv_bfloat16* Bh = g_w_h + (size_t)sel * (CC * (size_t)CC);
    const __nv_bfloat16* Bl = g_w_l + (size_t)sel * (CC * (size_t)CC);

    extern __shared__ unsigned sm_u[];
    int t = threadIdx.x;
    int m0 = blockIdx.y * 128, n0 = blockIdx.x * 128;
    int lane = t & 31;
    int g  = lane >> 2, tg = lane & 3;
    int wid = t >> 5, wm = wid & 1, wn = wid >> 1;   // warp tile 64x32

    // global -> smem staging: thread covers 16B of one row-half
    int lrow = t >> 1, lhalf = t & 1;
    const __nv_bfloat16* gp0 = Ah + (size_t)(m0 + lrow) * 1024 + lhalf * 8;
    const __nv_bfloat16* gp1 = Al + (size_t)(m0 + lrow) * 1024 + lhalf * 8;
    const __nv_bfloat16* gp2 = Bh + (size_t)(n0 + lrow) * 1024 + lhalf * 8;
    const __nv_bfloat16* gp3 = Bl + (size_t)(n0 + lrow) * 1024 + lhalf * 8;

    unsigned sbase = (unsigned)__cvta_generic_to_shared(sm_u);
    unsigned sdst  = sbase + (unsigned)(48 * lrow + 16 * lhalf);

    // fragment LDS offsets (u32 index within one matrix buffer)
    int ar[4], br[4];
    #pragma unroll
    for (int mi = 0; mi < 4; mi++) ar[mi] = (wm * 64 + mi * 16 + g) * 12 + tg;
    #pragma unroll
    for (int ni = 0; ni < 4; ni++) br[ni] = (wn * 32 + ni * 8 + g) * 12 + tg;

    float c[4][4][4];
    #pragma unroll
    for (int mi = 0; mi < 4; mi++)
        #pragma unroll
        for (int ni = 0; ni < 4; ni++)
            #pragma unroll
            for (int q = 0; q < 4; q++) c[mi][ni][q] = 0.f;

    // prologue: stage 0 -> buf 0
    CP16(sdst + 0u * (2*GU*4), gp0);
    CP16(sdst + 1u * (2*GU*4), gp1);
    CP16(sdst + 2u * (2*GU*4), gp2);
    CP16(sdst + 3u * (2*GU*4), gp3);
    asm volatile("cp.async.commit_group;");
    asm volatile("cp.async.wait_group 0;");
    __syncthreads();

    int buf = 0;
    #pragma unroll 1
    for (int kt = 0; kt < 64; kt++) {
        if (kt < 63) {
            int st = (kt + 1) * 16;
            unsigned d = sdst + (unsigned)((buf ^ 1) * (GU * 4));
            CP16(d + 0u * (2*GU*4), gp0 + st);
            CP16(d + 1u * (2*GU*4), gp1 + st);
            CP16(d + 2u * (2*GU*4), gp2 + st);
            CP16(d + 3u * (2*GU*4), gp3 + st);
            asm volatile("cp.async.commit_group;");
        }

        const unsigned* pAh = sm_u + 0 * 2 * GU + buf * GU;
        const unsigned* pAl = sm_u + 1 * 2 * GU + buf * GU;
        const unsigned* pBh = sm_u + 2 * 2 * GU + buf * GU;
        const unsigned* pBl = sm_u + 3 * 2 * GU + buf * GU;

        unsigned a[4][4];
        #pragma unroll
        for (int mi = 0; mi < 4; mi++) {
            a[mi][0] = pAh[ar[mi]];       a[mi][1] = pAh[ar[mi] + 96];
            a[mi][2] = pAh[ar[mi] + 4];   a[mi][3] = pAh[ar[mi] + 100];
        }
        #pragma unroll
        for (int ni = 0; ni < 4; ni++) {           // A_hi * B_hi
            unsigned b0 = pBh[br[ni]], b1 = pBh[br[ni] + 4];
            #pragma unroll
            for (int mi = 0; mi < 4; mi++) MMA_BF16(c[mi][ni], a[mi], b0, b1);
        }
        #pragma unroll
        for (int ni = 0; ni < 4; ni++) {           // A_hi * B_lo
            unsigned b0 = pBl[br[ni]], b1 = pBl[br[ni] + 4];
            #pragma unroll
            for (int mi = 0; mi < 4; mi++) MMA_BF16(c[mi][ni], a[mi], b0, b1);
        }
        #pragma unroll
        for (int mi = 0; mi < 4; mi++) {
            a[mi][0] = pAl[ar[mi]];       a[mi][1] = pAl[ar[mi] + 96];
            a[mi][2] = pAl[ar[mi] + 4];   a[mi][3] = pAl[ar[mi] + 100];
        }
        #pragma unroll
        for (int ni = 0; ni < 4; ni++) {           // A_lo * B_hi
            unsigned b0 = pBh[br[ni]], b1 = pBh[br[ni] + 4];
            #pragma unroll
            for (int mi = 0; mi < 4; mi++) MMA_BF16(c[mi][ni], a[mi], b0, b1);
        }

        asm volatile("cp.async.wait_group 0;");
        __syncthreads();
        buf ^= 1;
    }

    // epilogue
    #pragma unroll
    for (int mi = 0; mi < 4; mi++) {
        int mrow = m0 + wm * 64 + mi * 16 + g;
        #pragma unroll
        for (int ni = 0; ni < 4; ni++) {
            int ncol = n0 + wn * 32 + ni * 8 + 2 * tg;
            float2 v0 = make_float2(c[mi][ni][0], c[mi][ni][1]);
            float2 v1 = make_float2(c[mi][ni][2], c[mi][ni][3]);
            if (MODE == 0) {
                int bb = mrow >> 11, l = mrow & 2047, hh = ncol >> 6, d = ncol & 63;
                float* dst = (sel == 0) ? g_XQ : (sel == 1) ? g_XK : g_XV;
                size_t base = ((size_t)((bb << 4) + hh) << 17) + ((size_t)l << 6) + d;
                *(float2*)&dst[base] = v0;
                *(float2*)&dst[base + (8 << 6)] = v1;   // row mrow+8 (same b,h)
            } else {
                *(float2*)&Co[(size_t)mrow * 1024 + ncol] = v0;
                *(float2*)&Co[(size_t)(mrow + 8) * 1024 + ncol] = v1;
            }
        }
    }
}

// ---------------- RoPE: adjacent-pair rotation ----------------
__global__ __launch_bounds__(256) void rope_kernel()
{
    int p = blockIdx.x * 256 + threadIdx.x;
    int d2 = p & 31;
    int l  = (p >> 5) & 2047;
    int bh = p >> 16;
    size_t base = ((size_t)bh << 17) + ((size_t)l << 6) + 2 * d2;
    float inv = __expf(-(float)d2 * (9.21034037f / 32.f));
    float s, c;
    sincosf((float)(l & 15) * inv, &s, &c);
    float2 q = *(float2*)&g_XQ[base];
    float2 k = *(float2*)&g_XK[base];
    *(float2*)&g_XQ[base] = make_float2(q.x * c - q.y * s, q.y * c + q.x * s);
    *(float2*)&g_XK[base] = make_float2(k.x * c - k.y * s, k.y * c + k.x * s);
}

// ---------------- lr sigmoid ----------------
__global__ __launch_bounds__(256) void lr_kernel(const float* __restrict__ hs,
                                                 const float* __restrict__ lrw,
                                                 const float* __restrict__ lrb)
{
    __shared__ float row[1024];
    int bl = blockIdx.x, t = threadIdx.x;
    *(float4*)&row[t * 4] = *(const float4*)&hs[(size_t)bl * 1024 + t * 4];
    __syncthreads();
    int w = t >> 5, lane = t & 31;
    for (int hh = w; hh < 16; hh += 8) {
        float s = 0.f;
        const float* wv = lrw + hh * 1024;
        for (int c = lane; c < 1024; c += 32) s += row[c] * wv[c];
        #pragma unroll
        for (int o = 16; o; o >>= 1) s += __shfl_xor_sync(0xffffffffu, s, o);
        if (lane == 0)
            g_lr[(size_t)((bl >> 11) * 16 + hh) * 2048 + (bl & 2047)] =
                1.f / (1.f + __expf(-(s + lrb[hh])));
    }
}

// ---------------- post-LN in place ----------------
__global__ __launch_bounds__(256) void postln_kernel(const float* __restrict__ pw,
                                                     const float* __restrict__ pb)
{
    __shared__ float red[256];
    int m = blockIdx.x, t = threadIdx.x;
    float4 x = *(float4*)&g_XQW[(size_t)m * 1024 + t * 4];
    red[t] = x.x + x.y + x.z + x.w;
    __syncthreads();
    #pragma unroll
    for (int o = 128; o; o >>= 1) { if (t < o) red[t] += red[t + o]; __syncthreads(); }
    float mu = red[0] * (1.f / 1024.f);
    __syncthreads();
    float dx = x.x - mu, dy = x.y - mu, dz = x.z - mu, dw = x.w - mu;
    red[t] = dx*dx + dy*dy + dz*dz + dw*dw;
    __syncthreads();
    #pragma unroll
    for (int o = 128; o; o >>= 1) { if (t < o) red[t] += red[t + o]; __syncthreads(); }
    float rstd = rsqrtf(red[0] * (1.f / 1024.f) + EPSF);
    float4 w = *(const float4*)&pw[t * 4];
    float4 b = *(const float4*)&pb[t * 4];
    *(float4*)&g_XQW[(size_t)m * 1024 + t * 4] =
        make_float4(w.x*dx*rstd + b.x, w.y*dy*rstd + b.y, w.z*dz*rstd + b.z, w.w*dw*rstd + b.w);
}

// ---------------- TTT scan: one CTA per (b,h), state in SMEM (unchanged, passing) ----------------
#define SCAN_SMEM_BYTES (56016 * 4)

__global__ __launch_bounds__(256, 1) void scan_kernel(
    const float* __restrict__ lt_idx,
    const float* __restrict__ lnw_g, const float* __restrict__ lnb_g,
    const float* __restrict__ W1g,   const float* __restrict__ b1g,
    const float* __restrict__ W2g,   const float* __restrict__ b2g)
{
    extern __shared__ float sm[];
    float* sW1  = sm;            // [64][256]
    float* sW2  = sm + 16384;    // [256][65]
    float* sb1  = sm + 33024;
    float* sb2  = sm + 33280;
    float* sxq  = sm + 33344;    // [16][68]
    float* sxk  = sm + 34432;
    float* sxv  = sm + 35520;
    float* sZ1  = sm + 36608;    // [16][256]
    float* sX2  = sm + 40704;    // [16][260]
    float* sX2b = sm + 44864;    // [16][260]
    float* sG1  = sm + 49024;    // [16][256]
    float* sG2  = sm + 53120;    // [16][68]
    float* sZ2  = sm + 54208;    // [16][68]
    float* sA1  = sm + 55296;    // [16][17]
    float* sA2  = sm + 55568;    // [16][17]
    float* slnw = sm + 55840;
    float* slnb = sm + 55904;
    float* slrh = sm + 55968;
    float* stok = sm + 55984;
    float* slast= sm + 56000;

    int t = threadIdx.x;
    int bh = blockIdx.x;
    int b = bh >> 4, h = bh & 15;

    {
        const float* w1 = W1g + h * 16384;
        for (int i = t * 4; i < 16384; i += 1024)
            *(float4*)&sW1[i] = *(const float4*)&w1[i];
        const float* w2 = W2g + h * 16384 + t * 64;
        #pragma unroll
        for (int j = 0; j < 64; j += 4) {
            float4 v = *(const float4*)&w2[j];
            sW2[t*65+j] = v.x; sW2[t*65+j+1] = v.y; sW2[t*65+j+2] = v.z; sW2[t*65+j+3] = v.w;
        }
        sb1[t] = b1g[h * 256 + t];
        if (t < 64) { sb2[t] = b2g[h*64+t]; slnw[t] = lnw_g[h*64+t]; slnb[t] = lnb_g[h*64+t]; }
        if (t < 16) stok[t] = fmaxf(1.f / (float)(t + 1) + lt_idx[t], 0.f);
    }
    __syncthreads();

    const size_t xbase = (size_t)bh << 17;

    for (int n = 0; n < NCH; n++) {
        int l0 = n * 16;
        {
            int r = t >> 4, c = (t & 15) * 4;
            size_t g = xbase + (size_t)(l0 + r) * 64 + c;
            *(float4*)&sxq[r*68 + c] = *(const float4*)&g_XQ[g];
            *(float4*)&sxk[r*68 + c] = *(const float4*)&g_XK[g];
            *(float4*)&sxv[r*68 + c] = *(const float4*)&g_XV[g];
        }
        if (t < 16) {
            slrh[t] = (1.f / 64.f) * g_lr[(size_t)bh * LL + l0 + t];
        }
        __syncthreads();
        if (t < 16) slast[t] = stok[15] * slrh[t];

        {
            float acc[16];
            float bf = sb1[t];
            #pragma unroll
            for (int i = 0; i < 16; i++) acc[i] = bf;
            for (int d = 0; d < 64; d += 4) {
                float w0 = sW1[(d+0)*256+t], w1 = sW1[(d+1)*256+t];
                float w2 = sW1[(d+2)*256+t], w3 = sW1[(d+3)*256+t];
                #pragma unroll
                for (int i = 0; i < 16; i++) {
                    float4 x4 = *(float4*)&sxk[i*68 + d];
                    acc[i] += x4.x*w0 + x4.y*w1 + x4.z*w2 + x4.w*w3;
                }
            }
            #pragma unroll
            for (int i = 0; i < 16; i++) { sZ1[i*256+t] = acc[i]; sX2[i*260+t] = gelu_f(acc[i]); }
        }
        __syncthreads();

        {
            int jj = t & 63, i0 = (t >> 6) * 4;
            float z[4];
            float bz = sb2[jj];
            z[0] = z[1] = z[2] = z[3] = bz;
            for (int f = 0; f < 256; f += 4) {
                float w0 = sW2[(f+0)*65+jj], w1 = sW2[(f+1)*65+jj];
                float w2 = sW2[(f+2)*65+jj], w3 = sW2[(f+3)*65+jj];
                #pragma unroll
                for (int k = 0; k < 4; k++) {
                    float4 x4 = *(float4*)&sX2[(i0+k)*260 + f];
                    z[k] += x4.x*w0 + x4.y*w1 + x4.z*w2 + x4.w*w3;
                }
            }
            #pragma unroll
            for (int k = 0; k < 4; k++) sZ2[(i0+k)*68 + jj] = z[k];

            int ia = t & 15, ja = t >> 4;
            float dot = 0.f;
            for (int d = 0; d < 64; d += 4) {
                float4 q4 = *(float4*)&sxq[ia*68 + d];
                float4 k4 = *(float4*)&sxk[ja*68 + d];
                dot += q4.x*k4.x + q4.y*k4.y + q4.z*k4.z + q4.w*k4.w;
            }
            sA1[ia*17+ja] = (ja <= ia) ? stok[ia] * slrh[ja] * (dot + 1.f) : 0.f;
        }
        __syncthreads();

        {
            int w = t >> 5, lane = t & 31;
            #pragma unroll
            for (int rr = 0; rr < 2; rr++) {
                int i = w * 2 + rr;
                float z0 = sZ2[i*68+lane], z1 = sZ2[i*68+lane+32];
                float s = z0 + z1;
                #pragma unroll
                for (int o = 16; o; o >>= 1) s += __shfl_xor_sync(0xffffffffu, s, o);
                float mu = s * (1.f / 64.f);
                float d0 = z0 - mu, d1 = z1 - mu;
                float v = d0*d0 + d1*d1;
                #pragma unroll
                for (int o = 16; o; o >>= 1) v += __shfl_xor_sync(0xffffffffu, v, o);
                float rstd = rsqrtf(v * (1.f / 64.f) + EPSF);
                float xh0 = d0*rstd, xh1 = d1*rstd;
                float g0 = slnw[lane], g1 = slnw[lane+32];
                float tg0 = sxv[i*68+lane]    - sxk[i*68+lane];
                float tg1 = sxv[i*68+lane+32] - sxk[i*68+lane+32];
                float go0 = (g0*xh0 + slnb[lane]    - tg0) * g0;
                float go1 = (g1*xh1 + slnb[lane+32] - tg1) * g1;
                float s1 = go0 + go1, s2 = go0*xh0 + go1*xh1;
                #pragma unroll
                for (int o = 16; o; o >>= 1) {
                    s1 += __shfl_xor_sync(0xffffffffu, s1, o);
                    s2 += __shfl_xor_sync(0xffffffffu, s2, o);
                }
                float inv = rstd * (1.f / 64.f);
                sG2[i*68+lane]    = (64.f*go0 - s1 - xh0*s2) * inv;
                sG2[i*68+lane+32] = (64.f*go1 - s1 - xh1*s2) * inv;
            }
        }
        __syncthreads();

        {
            float acc[16];
            #pragma unroll
            for (int i = 0; i < 16; i++) acc[i] = 0.f;
            for (int j = 0; j < 64; j += 4) {
                float w0 = sW2[t*65+j],   w1 = sW2[t*65+j+1];
                float w2 = sW2[t*65+j+2], w3 = sW2[t*65+j+3];
                #pragma unroll
                for (int i = 0; i < 16; i++) {
                    float4 g4 = *(float4*)&sG2[i*68 + j];
                    acc[i] += g4.x*w0 + g4.y*w1 + g4.z*w2 + g4.w*w3;
                }
            }
            #pragma unroll
            for (int i = 0; i < 16; i++) sG1[i*256+t] = acc[i] * gelu_b(sZ1[i*256+t]);
        }
        __syncthreads();

        {
            float acc[16];
            float bf = sb1[t];
            #pragma unroll
            for (int i = 0; i < 16; i++) acc[i] = bf;
            for (int d = 0; d < 64; d += 4) {
                float w0 = sW1[(d+0)*256+t], w1 = sW1[(d+1)*256+t];
                float w2 = sW1[(d+2)*256+t], w3 = sW1[(d+3)*256+t];
                #pragma unroll
                for (int i = 0; i < 16; i++) {
                    float4 q4 = *(float4*)&sxq[i*68 + d];
                    acc[i] += q4.x*w0 + q4.y*w1 + q4.z*w2 + q4.w*w3;
                }
            }
            #pragma unroll
            for (int j = 0; j < 16; j++) {
                float g = sG1[j*256+t];
                #pragma unroll
                for (int i = j; i < 16; i++) acc[i] -= sA1[i*17+j] * g;
            }
            #pragma unroll
            for (int i = 0; i < 16; i++) sX2b[i*260+t] = gelu_f(acc[i]);
        }
        __syncthreads();

        {
            int ia = t & 15, ja = t >> 4;
            float dot = 0.f;
            for (int f = 0; f < 256; f += 4) {
                float4 a4 = *(float4*)&sX2b[ia*260 + f];
                float4 b4 = *(float4*)&sX2[ja*260 + f];
                dot += a4.x*b4.x + a4.y*b4.y + a4.z*b4.z + a4.w*b4.w;
            }
            sA2[ia*17+ja] = (ja <= ia) ? stok[ia] * slrh[ja] * (dot + 1.f) : 0.f;
        }
        __syncthreads();

        {
            int jj = t & 63, i0 = (t >> 6) * 4;
            float z[4];
            float bz = sb2[jj];
            z[0] = z[1] = z[2] = z[3] = bz;
            for (int f = 0; f < 256; f += 4) {
                float w0 = sW2[(f+0)*65+jj], w1 = sW2[(f+1)*65+jj];
                float w2 = sW2[(f+2)*65+jj], w3 = sW2[(f+3)*65+jj];
                #pragma unroll
                for (int k = 0; k < 4; k++) {
                    float4 x4 = *(float4*)&sX2b[(i0+k)*260 + f];
                    z[k] += x4.x*w0 + x4.y*w1 + x4.z*w2 + x4.w*w3;
                }
            }
            #pragma unroll
            for (int j = 0; j < 16; j++) {
                float g = sG2[j*68 + jj];
                #pragma unroll
                for (int k = 0; k < 4; k++)
                    if (j <= i0 + k) z[k] -= sA2[(i0+k)*17+j] * g;
            }
            #pragma unroll
            for (int k = 0; k < 4; k++) sZ2[(i0+k)*68 + jj] = z[k];
        }
        __syncthreads();

        {
            int w = t >> 5, lane = t & 31;
            #pragma unroll
            for (int rr = 0; rr < 2; rr++) {
                int i = w * 2 + rr;
                float z0 = sZ2[i*68+lane], z1 = sZ2[i*68+lane+32];
                float s = z0 + z1;
                #pragma unroll
                for (int o = 16; o; o >>= 1) s += __shfl_xor_sync(0xffffffffu, s, o);
                float mu = s * (1.f / 64.f);
                float d0 = z0 - mu, d1 = z1 - mu;
                float v = d0*d0 + d1*d1;
                #pragma unroll
                for (int o = 16; o; o >>= 1) v += __shfl_xor_sync(0xffffffffu, v, o);
                float rstd = rsqrtf(v * (1.f / 64.f) + EPSF);
                size_t orow = (size_t)(b * 2048 + l0 + i) * 1024 + h * 64;
                g_XQW[orow + lane]      = sxq[i*68+lane]    + slnw[lane]*d0*rstd    + slnb[lane];
                g_XQW[orow + lane + 32] = sxq[i*68+lane+32] + slnw[lane+32]*d1*rstd + slnb[lane+32];
            }
        }
        __syncthreads();

        {
            float g1s[16];
            #pragma unroll
            for (int j = 0; j < 16; j++) g1s[j] = sG1[j*256+t] * slast[j];
            float bs = 0.f;
            #pragma unroll
            for (int j = 0; j < 16; j++) bs += g1s[j];
            sb1[t] -= bs;
            #pragma unroll
            for (int d0 = 0; d0 < 64; d0 += 4) {
                float a0 = 0.f, a1 = 0.f, a2 = 0.f, a3 = 0.f;
                #pragma unroll
                for (int j = 0; j < 16; j++) {
                    float4 xk4 = *(float4*)&sxk[j*68 + d0];
                    a0 += xk4.x * g1s[j]; a1 += xk4.y * g1s[j];
                    a2 += xk4.z * g1s[j]; a3 += xk4.w * g1s[j];
                }
                sW1[(d0+0)*256+t] -= a0; sW1[(d0+1)*256+t] -= a1;
                sW1[(d0+2)*256+t] -= a2; sW1[(d0+3)*256+t] -= a3;
            }
            for (int idx = t; idx < 1024; idx += 256) {
                int j = idx >> 6, d = idx & 63;
                sG2[j*68 + d] *= slast[j];
            }
        }
        __syncthreads();

        {
            float x2s[16];
            #pragma unroll
            for (int j = 0; j < 16; j++) x2s[j] = sX2[j*260+t];
            #pragma unroll
            for (int jd = 0; jd < 64; jd += 4) {
                float a0 = 0.f, a1 = 0.f, a2 = 0.f, a3 = 0.f;
                #pragma unroll
                for (int j = 0; j < 16; j++) {
                    float4 g4 = *(float4*)&sG2[j*68 + jd];
                    a0 += g4.x * x2s[j]; a1 += g4.y * x2s[j];
                    a2 += g4.z * x2s[j]; a3 += g4.w * x2s[j];
                }
                sW2[t*65+jd]   -= a0; sW2[t*65+jd+1] -= a1;
                sW2[t*65+jd+2] -= a2; sW2[t*65+jd+3] -= a3;
            }
            if (t < 64) {
                float s = 0.f;
                #pragma unroll
                for (int j = 0; j < 16; j++) s += sG2[j*68 + t];
                sb2[t] -= s;
            }
        }
        __syncthreads();
    }
}

// ---------------- launch ----------------
extern "C" void kernel_launch(void* const* d_in, const int* in_sizes, int n_in,
                              void* d_out, int out_size)
{
    const float* hs   = (const float*)d_in[0];
    const float* wq   = (const float*)d_in[1];
    const float* wk   = (const float*)d_in[2];
    const float* wv   = (const float*)d_in[3];
    const float* wo   = (const float*)d_in[4];
    const float* lti  = (const float*)d_in[5];
    const float* lrw  = (const float*)d_in[6];
    const float* lrb  = (const float*)d_in[7];
    const float* lnw  = (const float*)d_in[8];
    const float* lnb  = (const float*)d_in[9];
    const float* pw   = (const float*)d_in[10];
    const float* pb   = (const float*)d_in[11];
    const float* W1   = (const float*)d_in[12];
    const float* b1   = (const float*)d_in[13];
    const float* W2   = (const float*)d_in[14];
    const float* b2   = (const float*)d_in[15];
    float* out = (float*)d_out;

    // Idempotent, not stream ops -> graph-capture safe; no static guards (rule).
    cudaFuncSetAttribute(scan_kernel, cudaFuncAttributeMaxDynamicSharedMemorySize,
                         SCAN_SMEM_BYTES);
    cudaFuncSetAttribute(bgemm_nt<0>, cudaFuncAttributeMaxDynamicSharedMemorySize,
                         BG_SMEM);
    cudaFuncSetAttribute(bgemm_nt<1>, cudaFuncAttributeMaxDynamicSharedMemorySize,
                         BG_SMEM);

    dim3 gg(8, 64), bt(256);

    // split inputs to bf16 hi/lo
    cvt_kernel<<<8192, 256>>>(hs, 0, 0, 2097152);
    cvt_kernel<<<1024, 256>>>(wq, 1, 0,       262144);
    cvt_kernel<<<1024, 256>>>(wk, 1, 1048576, 262144);
    cvt_kernel<<<1024, 256>>>(wv, 1, 2097152, 262144);
    cvt_kernel<<<1024, 256>>>(wo, 1, 3145728, 262144);

    // QKV projections on tensor cores
    bgemm_nt<0><<<gg, bt, BG_SMEM>>>(0, nullptr);
    bgemm_nt<0><<<gg, bt, BG_SMEM>>>(1, nullptr);
    bgemm_nt<0><<<gg, bt, BG_SMEM>>>(2, nullptr);

    rope_kernel<<<16384, 256>>>();
    lr_kernel<<<8192, 256>>>(hs, lrw, lrb);
    scan_kernel<<<64, 256, SCAN_SMEM_BYTES>>>(lti, lnw, lnb, W1, b1, W2, b2);
    postln_kernel<<<8192, 256>>>(pw, pb);

    // output projection on tensor cores
    cvt_kernel<<<8192, 256>>>(nullptr, 2, 0, 2097152);
    bgemm_nt<1><<<gg, bt, BG_SMEM>>>(3, out);
}

// round 16
// speedup vs baseline: 1.5760x; 1.3851x over previous
#include <cuda_runtime.h>
#include <cuda_bf16.h>
#include <math.h>

#define NH  16
#define HD  64
#define KC  16
#define F4  256
#define BB  4
#define LL  2048
#define CC  1024
#define NCH 128
#define EPSF 1e-6f

// ---------------- scratch (static device globals; no allocation) ----------------
__device__ float g_XQ[BB*NH*LL*HD];   // [b][h][l][d]
__device__ float g_XK[BB*NH*LL*HD];
__device__ float g_XV[BB*NH*LL*HD];
__device__ float g_lr[BB*NH*LL];      // sigmoid lr per (b,h,l)
__device__ float g_XQW[BB*LL*CC];     // scan output (fp32)

// bf16 hi/lo split scratch for tensor-core GEMMs
__device__ __nv_bfloat16 g_hs_h[BB*LL*CC], g_hs_l[BB*LL*CC];
__device__ __nv_bfloat16 g_w_h[4*CC*CC],   g_w_l[4*CC*CC];
__device__ __nv_bfloat16 g_xw_h[BB*LL*CC], g_xw_l[BB*LL*CC];

// ---------------- math ----------------
__device__ __forceinline__ float ftanh(float x) {
    float a = fminf(fmaxf(2.f * x, -60.f), 60.f);
    float e = __expf(a);
    return (e - 1.f) / (e + 1.f);
}
__device__ __forceinline__ float gelu_f(float x) {
    return 0.5f * x * (1.f + ftanh(0.79788456f * x * (1.f + 0.044715f * x * x)));
}
__device__ __forceinline__ float gelu_b(float x) {
    float t = ftanh(0.79788456f * x * (1.f + 0.044715f * x * x));
    return 0.5f * x * ((1.f - t * t) * (0.79788456f + 0.1070322243f * x * x)) + 0.5f * (1.f + t);
}

// ---------------- cluster helpers ----------------
#define CLUSTER_SYNC() do { \
    asm volatile("barrier.cluster.arrive.aligned;" ::: "memory"); \
    asm volatile("barrier.cluster.wait.aligned;" ::: "memory"); \
} while (0)

__device__ __forceinline__ unsigned cl_rank() {
    unsigned r; asm("mov.u32 %0, %%cluster_ctarank;" : "=r"(r)); return r;
}
__device__ __forceinline__ unsigned cl_mapa(unsigned addr, unsigned rank) {
    unsigned r; asm("mapa.shared::cluster.u32 %0, %1, %2;" : "=r"(r) : "r"(addr), "r"(rank));
    return r;
}
__device__ __forceinline__ float ld_cl(unsigned a) {
    float v; asm volatile("ld.shared::cluster.f32 %0, [%1];" : "=f"(v) : "r"(a)); return v;
}

// ---------------- fp32 -> bf16 hi/lo split ----------------
__global__ __launch_bounds__(256) void cvt_kernel(const float* __restrict__ src,
                                                  int dst_sel, size_t dst_off, int n4)
{
    int i = blockIdx.x * 256 + threadIdx.x;
    if (i >= n4) return;
    __nv_bfloat16 *H, *L;
    if (dst_sel == 0) { H = g_hs_h; L = g_hs_l; }
    else              { H = g_w_h;  L = g_w_l;  }
    H += dst_off; L += dst_off;
    float4 v = ((const float4*)src)[i];
    __nv_bfloat16 h[4], l[4];
    h[0] = __float2bfloat16(v.x); l[0] = __float2bfloat16(v.x - __bfloat162float(h[0]));
    h[1] = __float2bfloat16(v.y); l[1] = __float2bfloat16(v.y - __bfloat162float(h[1]));
    h[2] = __float2bfloat16(v.z); l[2] = __float2bfloat16(v.z - __bfloat162float(h[2]));
    h[3] = __float2bfloat16(v.w); l[3] = __float2bfloat16(v.w - __bfloat162float(h[3]));
    *(uint2*)&H[(size_t)i * 4] = *(uint2*)h;
    *(uint2*)&L[(size_t)i * 4] = *(uint2*)l;
}

// ---------------- bf16 3-product tensor-core NT GEMM (unchanged, passing) ----------------
#define GU (128*12)
#define BG_SMEM (8*GU*4)

#define CP16(saddr, gptr) \
    asm volatile("cp.async.cg.shared.global [%0], [%1], 16;" :: "r"(saddr), "l"(gptr))

#define MMA_BF16(cc, aa, b0, b1) \
    asm volatile("mma.sync.aligned.m16n8k16.row.col.f32.bf16.bf16.f32 " \
        "{%0,%1,%2,%3}, {%4,%5,%6,%7}, {%8,%9}, {%0,%1,%2,%3};" \
        : "+f"(cc[0]), "+f"(cc[1]), "+f"(cc[2]), "+f"(cc[3]) \
        : "r"(aa[0]), "r"(aa[1]), "r"(aa[2]), "r"(aa[3]), "r"(b0), "r"(b1))

template<int MODE>
__global__ __launch_bounds__(256, 2) void bgemm_nt(int sel, float* __restrict__ Co)
{
    const __nv_bfloat16* Ah = (MODE == 0) ? g_hs_h : g_xw_h;
    const __nv_bfloat16* Al = (MODE == 0) ? g_hs_l : g_xw_l;
    const __nv_bfloat16* Bh = g_w_h + (size_t)sel * (CC * (size_t)CC);
    const __nv_bfloat16* Bl = g_w_l + (size_t)sel * (CC * (size_t)CC);

    extern __shared__ unsigned sm_u[];
    int t = threadIdx.x;
    int m0 = blockIdx.y * 128, n0 = blockIdx.x * 128;
    int lane = t & 31;
    int g  = lane >> 2, tg = lane & 3;
    int wid = t >> 5, wm = wid & 1, wn = wid >> 1;

    int lrow = t >> 1, lhalf = t & 1;
    const __nv_bfloat16* gp0 = Ah + (size_t)(m0 + lrow) * 1024 + lhalf * 8;
    const __nv_bfloat16* gp1 = Al + (size_t)(m0 + lrow) * 1024 + lhalf * 8;
    const __nv_bfloat16* gp2 = Bh + (size_t)(n0 + lrow) * 1024 + lhalf * 8;
    const __nv_bfloat16* gp3 = Bl + (size_t)(n0 + lrow) * 1024 + lhalf * 8;

    unsigned sbase = (unsigned)__cvta_generic_to_shared(sm_u);
    unsigned sdst  = sbase + (unsigned)(48 * lrow + 16 * lhalf);

    int ar[4], br[4];
    #pragma unroll
    for (int mi = 0; mi < 4; mi++) ar[mi] = (wm * 64 + mi * 16 + g) * 12 + tg;
    #pragma unroll
    for (int ni = 0; ni < 4; ni++) br[ni] = (wn * 32 + ni * 8 + g) * 12 + tg;

    float c[4][4][4];
    #pragma unroll
    for (int mi = 0; mi < 4; mi++)
        #pragma unroll
        for (int ni = 0; ni < 4; ni++)
            #pragma unroll
            for (int q = 0; q < 4; q++) c[mi][ni][q] = 0.f;

    CP16(sdst + 0u * (2*GU*4), gp0);
    CP16(sdst + 1u * (2*GU*4), gp1);
    CP16(sdst + 2u * (2*GU*4), gp2);
    CP16(sdst + 3u * (2*GU*4), gp3);
    asm volatile("cp.async.commit_group;");
    asm volatile("cp.async.wait_group 0;");
    __syncthreads();

    int buf = 0;
    #pragma unroll 1
    for (int kt = 0; kt < 64; kt++) {
        if (kt < 63) {
            int st = (kt + 1) * 16;
            unsigned d = sdst + (unsigned)((buf ^ 1) * (GU * 4));
            CP16(d + 0u * (2*GU*4), gp0 + st);
            CP16(d + 1u * (2*GU*4), gp1 + st);
            CP16(d + 2u * (2*GU*4), gp2 + st);
            CP16(d + 3u * (2*GU*4), gp3 + st);
            asm volatile("cp.async.commit_group;");
        }

        const unsigned* pAh = sm_u + 0 * 2 * GU + buf * GU;
        const unsigned* pAl = sm_u + 1 * 2 * GU + buf * GU;
        const unsigned* pBh = sm_u + 2 * 2 * GU + buf * GU;
        const unsigned* pBl = sm_u + 3 * 2 * GU + buf * GU;

        unsigned a[4][4];
        #pragma unroll
        for (int mi = 0; mi < 4; mi++) {
            a[mi][0] = pAh[ar[mi]];       a[mi][1] = pAh[ar[mi] + 96];
            a[mi][2] = pAh[ar[mi] + 4];   a[mi][3] = pAh[ar[mi] + 100];
        }
        #pragma unroll
        for (int ni = 0; ni < 4; ni++) {
            unsigned b0 = pBh[br[ni]], b1 = pBh[br[ni] + 4];
            #pragma unroll
            for (int mi = 0; mi < 4; mi++) MMA_BF16(c[mi][ni], a[mi], b0, b1);
        }
        #pragma unroll
        for (int ni = 0; ni < 4; ni++) {
            unsigned b0 = pBl[br[ni]], b1 = pBl[br[ni] + 4];
            #pragma unroll
            for (int mi = 0; mi < 4; mi++) MMA_BF16(c[mi][ni], a[mi], b0, b1);
        }
        #pragma unroll
        for (int mi = 0; mi < 4; mi++) {
            a[mi][0] = pAl[ar[mi]];       a[mi][1] = pAl[ar[mi] + 96];
            a[mi][2] = pAl[ar[mi] + 4];   a[mi][3] = pAl[ar[mi] + 100];
        }
        #pragma unroll
        for (int ni = 0; ni < 4; ni++) {
            unsigned b0 = pBh[br[ni]], b1 = pBh[br[ni] + 4];
            #pragma unroll
            for (int mi = 0; mi < 4; mi++) MMA_BF16(c[mi][ni], a[mi], b0, b1);
        }

        asm volatile("cp.async.wait_group 0;");
        __syncthreads();
        buf ^= 1;
    }

    #pragma unroll
    for (int mi = 0; mi < 4; mi++) {
        int mrow = m0 + wm * 64 + mi * 16 + g;
        #pragma unroll
        for (int ni = 0; ni < 4; ni++) {
            int ncol = n0 + wn * 32 + ni * 8 + 2 * tg;
            float2 v0 = make_float2(c[mi][ni][0], c[mi][ni][1]);
            float2 v1 = make_float2(c[mi][ni][2], c[mi][ni][3]);
            if (MODE == 0) {
                int bb = mrow >> 11, l = mrow & 2047, hh = ncol >> 6, d = ncol & 63;
                float* dst = (sel == 0) ? g_XQ : (sel == 1) ? g_XK : g_XV;
                size_t base = ((size_t)((bb << 4) + hh) << 17) + ((size_t)l << 6) + d;
                *(float2*)&dst[base] = v0;
                *(float2*)&dst[base + (8 << 6)] = v1;
            } else {
                *(float2*)&Co[(size_t)mrow * 1024 + ncol] = v0;
                *(float2*)&Co[(size_t)(mrow + 8) * 1024 + ncol] = v1;
            }
        }
    }
}

// ---------------- RoPE ----------------
__global__ __launch_bounds__(256) void rope_kernel()
{
    int p = blockIdx.x * 256 + threadIdx.x;
    int d2 = p & 31;
    int l  = (p >> 5) & 2047;
    int bh = p >> 16;
    size_t base = ((size_t)bh << 17) + ((size_t)l << 6) + 2 * d2;
    float inv = __expf(-(float)d2 * (9.21034037f / 32.f));
    float s, c;
    sincosf((float)(l & 15) * inv, &s, &c);
    float2 q = *(float2*)&g_XQ[base];
    float2 k = *(float2*)&g_XK[base];
    *(float2*)&g_XQ[base] = make_float2(q.x * c - q.y * s, q.y * c + q.x * s);
    *(float2*)&g_XK[base] = make_float2(k.x * c - k.y * s, k.y * c + k.x * s);
}

// ---------------- lr sigmoid ----------------
__global__ __launch_bounds__(256) void lr_kernel(const float* __restrict__ hs,
                                                 const float* __restrict__ lrw,
                                                 const float* __restrict__ lrb)
{
    __shared__ float row[1024];
    int bl = blockIdx.x, t = threadIdx.x;
    *(float4*)&row[t * 4] = *(const float4*)&hs[(size_t)bl * 1024 + t * 4];
    __syncthreads();
    int w = t >> 5, lane = t & 31;
    for (int hh = w; hh < 16; hh += 8) {
        float s = 0.f;
        const float* wv = lrw + hh * 1024;
        for (int c = lane; c < 1024; c += 32) s += row[c] * wv[c];
        #pragma unroll
        for (int o = 16; o; o >>= 1) s += __shfl_xor_sync(0xffffffffu, s, o);
        if (lane == 0)
            g_lr[(size_t)((bl >> 11) * 16 + hh) * 2048 + (bl & 2047)] =
                1.f / (1.f + __expf(-(s + lrb[hh])));
    }
}

// ---------------- post-LN + fused bf16 hi/lo output split ----------------
__global__ __launch_bounds__(256) void postln_kernel(const float* __restrict__ pw,
                                                     const float* __restrict__ pb)
{
    __shared__ float red[256];
    int m = blockIdx.x, t = threadIdx.x;
    float4 x = *(float4*)&g_XQW[(size_t)m * 1024 + t * 4];
    red[t] = x.x + x.y + x.z + x.w;
    __syncthreads();
    #pragma unroll
    for (int o = 128; o; o >>= 1) { if (t < o) red[t] += red[t + o]; __syncthreads(); }
    float mu = red[0] * (1.f / 1024.f);
    __syncthreads();
    float dx = x.x - mu, dy = x.y - mu, dz = x.z - mu, dw = x.w - mu;
    red[t] = dx*dx + dy*dy + dz*dz + dw*dw;
    __syncthreads();
    #pragma unroll
    for (int o = 128; o; o >>= 1) { if (t < o) red[t] += red[t + o]; __syncthreads(); }
    float rstd = rsqrtf(red[0] * (1.f / 1024.f) + EPSF);
    float4 w = *(const float4*)&pw[t * 4];
    float4 b = *(const float4*)&pb[t * 4];
    float r0 = w.x*dx*rstd + b.x, r1 = w.y*dy*rstd + b.y;
    float r2 = w.z*dz*rstd + b.z, r3 = w.w*dw*rstd + b.w;
    __nv_bfloat16 h4[4], l4[4];
    h4[0] = __float2bfloat16(r0); l4[0] = __float2bfloat16(r0 - __bfloat162float(h4[0]));
    h4[1] = __float2bfloat16(r1); l4[1] = __float2bfloat16(r1 - __bfloat162float(h4[1]));
    h4[2] = __float2bfloat16(r2); l4[2] = __float2bfloat16(r2 - __bfloat162float(h4[2]));
    h4[3] = __float2bfloat16(r3); l4[3] = __float2bfloat16(r3 - __bfloat162float(h4[3]));
    size_t o4 = (size_t)m * 1024 + t * 4;
    *(uint2*)&g_xw_h[o4] = *(uint2*)h4;
    *(uint2*)&g_xw_l[o4] = *(uint2*)l4;
}

// ---------------- TTT scan v2: 2-CTA cluster per (b,h), f-dim split ----------------
// SMEM float offsets
#define O_W1H   0        // [64][128]
#define O_W2H   8192     // [128][65]
#define O_B1H   16512    // [128]
#define O_B2    16640    // [64]
#define O_XQ    16704    // [16][68]
#define O_XK    17792
#define O_XV    18880
#define O_Z1H   19968    // [16][128]
#define O_X2H   22016    // [16][132]
#define O_X2BH  24128    // [16][132]
#define O_G1H   26240    // [16][128]
#define O_G2    28288    // [16][68]
#define O_Z2    29376    // [16][68]
#define O_PZ2   30464    // [16][68]  exchange buf 1
#define O_PZB   31552    // [16][68]  exchange buf 3
#define O_PA2   32640    // [16][17]  exchange buf 2
#define O_A1    32912    // [16][17]
#define O_A2    33184    // [16][17]
#define O_LNW   33456
#define O_LNB   33520
#define O_LRH   33584
#define O_TOK   33600
#define O_LAST  33616
#define SCAN2_FLOATS 33632
#define SCAN2_SMEM (SCAN2_FLOATS * 4)

__global__ __launch_bounds__(256, 1) __cluster_dims__(2, 1, 1)
void scan2_kernel(const float* __restrict__ lt_idx,
                  const float* __restrict__ lnw_g, const float* __restrict__ lnb_g,
                  const float* __restrict__ W1g,   const float* __restrict__ b1g,
                  const float* __restrict__ W2g,   const float* __restrict__ b2g)
{
    extern __shared__ float sm[];
    float* sW1h = sm + O_W1H;
    float* sW2h = sm + O_W2H;
    float* sb1h = sm + O_B1H;
    float* sb2  = sm + O_B2;
    float* sxq  = sm + O_XQ;
    float* sxk  = sm + O_XK;
    float* sxv  = sm + O_XV;
    float* sZ1h = sm + O_Z1H;
    float* sX2h = sm + O_X2H;
    float* sX2bh= sm + O_X2BH;
    float* sG1h = sm + O_G1H;
    float* sG2  = sm + O_G2;
    float* sZ2  = sm + O_Z2;
    float* sPZ2 = sm + O_PZ2;
    float* sPZB = sm + O_PZB;
    float* sPA2 = sm + O_PA2;
    float* sA1  = sm + O_A1;
    float* sA2  = sm + O_A2;
    float* slnw = sm + O_LNW;
    float* slnb = sm + O_LNB;
    float* slrh = sm + O_LRH;
    float* stok = sm + O_TOK;
    float* slast= sm + O_LAST;

    int t = threadIdx.x;
    unsigned half = cl_rank();          // 0 or 1 : owns f in [half*128, half*128+128)
    int bh = blockIdx.x >> 1;
    int b = bh >> 4, h = bh & 15;

    unsigned smem_b = (unsigned)__cvta_generic_to_shared(sm);
    unsigned peer = half ^ 1u;
    unsigned pPZ2 = cl_mapa(smem_b + O_PZ2 * 4, peer);
    unsigned pPZB = cl_mapa(smem_b + O_PZB * 4, peer);
    unsigned pPA2 = cl_mapa(smem_b + O_PA2 * 4, peer);

    int fl = t & 127, rh = t >> 7;      // column + row-half mapping
    int jj = t & 63,  i0 = (t >> 6) * 4; // Z2-style mapping

    // ---- load state (this CTA's f-half) ----
    {
        for (int i = t * 4; i < 8192; i += 1024) {
            int d = i >> 7, c = i & 127;
            *(float4*)&sW1h[i] =
                *(const float4*)&W1g[h * 16384 + d * 256 + (int)half * 128 + c];
        }
        int fr = t >> 1, jh = (t & 1) * 32;
        const float* w2 = W2g + h * 16384 + ((int)half * 128 + fr) * 64 + jh;
        #pragma unroll
        for (int j = 0; j < 32; j += 4) {
            float4 v = *(const float4*)&w2[j];
            sW2h[fr*65 + jh + j]   = v.x; sW2h[fr*65 + jh + j+1] = v.y;
            sW2h[fr*65 + jh + j+2] = v.z; sW2h[fr*65 + jh + j+3] = v.w;
        }
        if (t < 128) sb1h[t] = b1g[h * 256 + (int)half * 128 + t];
        if (t < 64) { sb2[t] = b2g[h*64+t]; slnw[t] = lnw_g[h*64+t]; slnb[t] = lnb_g[h*64+t]; }
        if (t < 16) stok[t] = fmaxf(1.f / (float)(t + 1) + lt_idx[t], 0.f);
    }
    __syncthreads();

    const size_t xbase = (size_t)bh << 17;

    for (int n = 0; n < NCH; n++) {
        int l0 = n * 16;
        // ---- load chunk (full, both CTAs) ----
        {
            int r = t >> 4, c = (t & 15) * 4;
            size_t g = xbase + (size_t)(l0 + r) * 64 + c;
            *(float4*)&sxq[r*68 + c] = *(const float4*)&g_XQ[g];
            *(float4*)&sxk[r*68 + c] = *(const float4*)&g_XK[g];
            *(float4*)&sxv[r*68 + c] = *(const float4*)&g_XV[g];
        }
        if (t < 16) slrh[t] = (1.f / 64.f) * g_lr[(size_t)bh * LL + l0 + t];
        __syncthreads();
        if (t < 16) slast[t] = stok[15] * slrh[t];

        // ---- Z1h = xk@W1h + b1h ; X2h = gelu  (thread: col fl, rows rh*8..rh*8+7) ----
        {
            float acc[8];
            float bf = sb1h[fl];
            #pragma unroll
            for (int i = 0; i < 8; i++) acc[i] = bf;
            for (int d = 0; d < 64; d += 4) {
                float w0 = sW1h[(d+0)*128+fl], w1 = sW1h[(d+1)*128+fl];
                float w2 = sW1h[(d+2)*128+fl], w3 = sW1h[(d+3)*128+fl];
                #pragma unroll
                for (int i = 0; i < 8; i++) {
                    float4 x4 = *(float4*)&sxk[(rh*8+i)*68 + d];
                    acc[i] += x4.x*w0 + x4.y*w1 + x4.z*w2 + x4.w*w3;
                }
            }
            #pragma unroll
            for (int i = 0; i < 8; i++) {
                sZ1h[(rh*8+i)*128+fl] = acc[i];
                sX2h[(rh*8+i)*132+fl] = gelu_f(acc[i]);
            }
        }
        __syncthreads();

        // ---- Z2 partial (local f) ; A1 coefs (replicated) ----
        {
            float z[4] = {0.f, 0.f, 0.f, 0.f};
            for (int f = 0; f < 128; f += 4) {
                float w0 = sW2h[(f+0)*65+jj], w1 = sW2h[(f+1)*65+jj];
                float w2 = sW2h[(f+2)*65+jj], w3 = sW2h[(f+3)*65+jj];
                #pragma unroll
                for (int k = 0; k < 4; k++) {
                    float4 x4 = *(float4*)&sX2h[(i0+k)*132 + f];
                    z[k] += x4.x*w0 + x4.y*w1 + x4.z*w2 + x4.w*w3;
                }
            }
            #pragma unroll
            for (int k = 0; k < 4; k++) sPZ2[(i0+k)*68 + jj] = z[k];

            int ia = t & 15, ja = t >> 4;
            float dot = 0.f;
            for (int d = 0; d < 64; d += 4) {
                float4 q4 = *(float4*)&sxq[ia*68 + d];
                float4 k4 = *(float4*)&sxk[ja*68 + d];
                dot += q4.x*k4.x + q4.y*k4.y + q4.z*k4.z + q4.w*k4.w;
            }
            sA1[ia*17+ja] = (ja <= ia) ? stok[ia] * slrh[ja] * (dot + 1.f) : 0.f;
        }
        __syncthreads();
        CLUSTER_SYNC();                                     // CS1: sPZ2 both sides ready

        // ---- combine Z2 = local + peer + b2 ----
        {
            float bz = sb2[jj];
            #pragma unroll
            for (int k = 0; k < 4; k++) {
                int idx = (i0+k)*68 + jj;
                sZ2[idx] = sPZ2[idx] + ld_cl(pPZ2 + (unsigned)idx * 4) + bz;
            }
        }
        __syncthreads();

        // ---- gZ2 (replicated; warp per 2 rows) ----
        {
            int w = t >> 5, lane = t & 31;
            #pragma unroll
            for (int rr = 0; rr < 2; rr++) {
                int i = w * 2 + rr;
                float z0 = sZ2[i*68+lane], z1 = sZ2[i*68+lane+32];
                float s = z0 + z1;
                #pragma unroll
                for (int o = 16; o; o >>= 1) s += __shfl_xor_sync(0xffffffffu, s, o);
                float mu = s * (1.f / 64.f);
                float d0 = z0 - mu, d1 = z1 - mu;
                float v = d0*d0 + d1*d1;
                #pragma unroll
                for (int o = 16; o; o >>= 1) v += __shfl_xor_sync(0xffffffffu, v, o);
                float rstd = rsqrtf(v * (1.f / 64.f) + EPSF);
                float xh0 = d0*rstd, xh1 = d1*rstd;
                float g0 = slnw[lane], g1 = slnw[lane+32];
                float tg0 = sxv[i*68+lane]    - sxk[i*68+lane];
                float tg1 = sxv[i*68+lane+32] - sxk[i*68+lane+32];
                float go0 = (g0*xh0 + slnb[lane]    - tg0) * g0;
                float go1 = (g1*xh1 + slnb[lane+32] - tg1) * g1;
                float s1 = go0 + go1, s2 = go0*xh0 + go1*xh1;
                #pragma unroll
                for (int o = 16; o; o >>= 1) {
                    s1 += __shfl_xor_sync(0xffffffffu, s1, o);
                    s2 += __shfl_xor_sync(0xffffffffu, s2, o);
                }
                float inv = rstd * (1.f / 64.f);
                sG2[i*68+lane]    = (64.f*go0 - s1 - xh0*s2) * inv;
                sG2[i*68+lane+32] = (64.f*go1 - s1 - xh1*s2) * inv;
            }
        }
        __syncthreads();

        // ---- gZ1h = (gZ2 @ W2h^T) * gelu'(Z1h) ----
        {
            float acc[8];
            #pragma unroll
            for (int i = 0; i < 8; i++) acc[i] = 0.f;
            for (int j = 0; j < 64; j += 4) {
                float w0 = sW2h[fl*65+j],   w1 = sW2h[fl*65+j+1];
                float w2 = sW2h[fl*65+j+2], w3 = sW2h[fl*65+j+3];
                #pragma unroll
                for (int i = 0; i < 8; i++) {
                    float4 g4 = *(float4*)&sG2[(rh*8+i)*68 + j];
                    acc[i] += g4.x*w0 + g4.y*w1 + g4.z*w2 + g4.w*w3;
                }
            }
            #pragma unroll
            for (int i = 0; i < 8; i++)
                sG1h[(rh*8+i)*128+fl] = acc[i] * gelu_b(sZ1h[(rh*8+i)*128+fl]);
        }
        __syncthreads();

        // ---- Z1_bar h = xq@W1h + b1h - A1@gZ1h ; X2bh = gelu ----
        {
            float acc[8];
            float bf = sb1h[fl];
            #pragma unroll
            for (int i = 0; i < 8; i++) acc[i] = bf;
            for (int d = 0; d < 64; d += 4) {
                float w0 = sW1h[(d+0)*128+fl], w1 = sW1h[(d+1)*128+fl];
                float w2 = sW1h[(d+2)*128+fl], w3 = sW1h[(d+3)*128+fl];
                #pragma unroll
                for (int i = 0; i < 8; i++) {
                    float4 q4 = *(float4*)&sxq[(rh*8+i)*68 + d];
                    acc[i] += q4.x*w0 + q4.y*w1 + q4.z*w2 + q4.w*w3;
                }
            }
            #pragma unroll
            for (int j = 0; j < 16; j++) {
                float g = sG1h[j*128+fl];
                #pragma unroll
                for (int i = 0; i < 8; i++) {
                    int r = rh*8 + i;
                    if (j <= r) acc[i] -= sA1[r*17+j] * g;
                }
            }
            #pragma unroll
            for (int i = 0; i < 8; i++) sX2bh[(rh*8+i)*132+fl] = gelu_f(acc[i]);
        }
        __syncthreads();

        // ---- A2 partial (local f) ----
        {
            int ia = t & 15, ja = t >> 4;
            float dot = 0.f;
            for (int f = 0; f < 128; f += 4) {
                float4 a4 = *(float4*)&sX2bh[ia*132 + f];
                float4 b4 = *(float4*)&sX2h[ja*132 + f];
                dot += a4.x*b4.x + a4.y*b4.y + a4.z*b4.z + a4.w*b4.w;
            }
            sPA2[ia*17+ja] = dot;
        }
        __syncthreads();
        CLUSTER_SYNC();                                     // CS2: sPA2 ready

        // ---- combine A2 ----
        {
            int ia = t & 15, ja = t >> 4;
            int idx = ia*17 + ja;
            float dot = sPA2[idx] + ld_cl(pPA2 + (unsigned)idx * 4);
            sA2[idx] = (ja <= ia) ? stok[ia] * slrh[ja] * (dot + 1.f) : 0.f;
        }
        __syncthreads();

        // ---- Z2_bar partial (local f) ----
        {
            float z[4] = {0.f, 0.f, 0.f, 0.f};
            for (int f = 0; f < 128; f += 4) {
                float w0 = sW2h[(f+0)*65+jj], w1 = sW2h[(f+1)*65+jj];
                float w2 = sW2h[(f+2)*65+jj], w3 = sW2h[(f+3)*65+jj];
                #pragma unroll
                for (int k = 0; k < 4; k++) {
                    float4 x4 = *(float4*)&sX2bh[(i0+k)*132 + f];
                    z[k] += x4.x*w0 + x4.y*w1 + x4.z*w2 + x4.w*w3;
                }
            }
            #pragma unroll
            for (int k = 0; k < 4; k++) sPZB[(i0+k)*68 + jj] = z[k];
        }
        __syncthreads();
        CLUSTER_SYNC();                                     // CS3: sPZB ready

        // ---- combine Z2_bar = local + peer + b2 - A2@gZ2 ----
        {
            float bz = sb2[jj];
            #pragma unroll
            for (int k = 0; k < 4; k++) {
                int r = i0 + k;
                int idx = r*68 + jj;
                float z = sPZB[idx] + ld_cl(pPZB + (unsigned)idx * 4) + bz;
                for (int j = 0; j <= r; j++)
                    z -= sA2[r*17+j] * sG2[j*68 + jj];
                sZ2[idx] = z;
            }
        }
        __syncthreads();

        // ---- output: xq + ln_fwd(Z2_bar); CTA writes its 8 rows ----
        {
            int lane = t & 31;
            int i = (int)half * 8 + (t >> 5);
            float z0 = sZ2[i*68+lane], z1 = sZ2[i*68+lane+32];
            float s = z0 + z1;
            #pragma unroll
            for (int o = 16; o; o >>= 1) s += __shfl_xor_sync(0xffffffffu, s, o);
            float mu = s * (1.f / 64.f);
            float d0 = z0 - mu, d1 = z1 - mu;
            float v = d0*d0 + d1*d1;
            #pragma unroll
            for (int o = 16; o; o >>= 1) v += __shfl_xor_sync(0xffffffffu, v, o);
            float rstd = rsqrtf(v * (1.f / 64.f) + EPSF);
            size_t orow = (size_t)(b * 2048 + l0 + i) * 1024 + h * 64;
            g_XQW[orow + lane]      = sxq[i*68+lane]    + slnw[lane]*d0*rstd    + slnb[lane];
            g_XQW[orow + lane + 32] = sxq[i*68+lane+32] + slnw[lane+32]*d1*rstd + slnb[lane+32];
        }
        __syncthreads();

        // ---- phase A: W1h/b1h update + scale sG2 in place ----
        {
            int dh = t >> 7;
            float g1s[16];
            #pragma unroll
            for (int j = 0; j < 16; j++) g1s[j] = sG1h[j*128+fl] * slast[j];
            if (dh == 0) {
                float bs = 0.f;
                #pragma unroll
                for (int j = 0; j < 16; j++) bs += g1s[j];
                sb1h[fl] -= bs;
            }
            #pragma unroll
            for (int d0 = 0; d0 < 32; d0 += 4) {
                int d = dh * 32 + d0;
                float a0 = 0.f, a1 = 0.f, a2 = 0.f, a3 = 0.f;
                #pragma unroll
                for (int j = 0; j < 16; j++) {
                    float4 xk4 = *(float4*)&sxk[j*68 + d];
                    a0 += xk4.x * g1s[j]; a1 += xk4.y * g1s[j];
                    a2 += xk4.z * g1s[j]; a3 += xk4.w * g1s[j];
                }
                sW1h[(d+0)*128+fl] -= a0; sW1h[(d+1)*128+fl] -= a1;
                sW1h[(d+2)*128+fl] -= a2; sW1h[(d+3)*128+fl] -= a3;
            }
            for (int idx = t; idx < 1024; idx += 256)
                sG2[(idx >> 6)*68 + (idx & 63)] *= slast[idx >> 6];
        }
        __syncthreads();

        // ---- phase B: W2h/b2 update ----
        {
            int jh = t >> 7;
            float x2s[16];
            #pragma unroll
            for (int j = 0; j < 16; j++) x2s[j] = sX2h[j*132+fl];
            #pragma unroll
            for (int jd0 = 0; jd0 < 32; jd0 += 4) {
                int jd = jh * 32 + jd0;
                float a0 = 0.f, a1 = 0.f, a2 = 0.f, a3 = 0.f;
                #pragma unroll
                for (int j = 0; j < 16; j++) {
                    float4 g4 = *(float4*)&sG2[j*68 + jd];
                    a0 += g4.x * x2s[j]; a1 += g4.y * x2s[j];
                    a2 += g4.z * x2s[j]; a3 += g4.w * x2s[j];
                }
                sW2h[fl*65+jd]   -= a0; sW2h[fl*65+jd+1] -= a1;
                sW2h[fl*65+jd+2] -= a2; sW2h[fl*65+jd+3] -= a3;
            }
            if (t < 64) {
                float s = 0.f;
                #pragma unroll
                for (int j = 0; j < 16; j++) s += sG2[j*68 + t];
                sb2[t] -= s;
            }
        }
        __syncthreads();
    }

    CLUSTER_SYNC();   // no CTA exits while peer may still read its SMEM
}

// ---------------- launch ----------------
extern "C" void kernel_launch(void* const* d_in, const int* in_sizes, int n_in,
                              void* d_out, int out_size)
{
    const float* hs   = (const float*)d_in[0];
    const float* wq   = (const float*)d_in[1];
    const float* wk   = (const float*)d_in[2];
    const float* wv   = (const float*)d_in[3];
    const float* wo   = (const float*)d_in[4];
    const float* lti  = (const float*)d_in[5];
    const float* lrw  = (const float*)d_in[6];
    const float* lrb  = (const float*)d_in[7];
    const float* lnw  = (const float*)d_in[8];
    const float* lnb  = (const float*)d_in[9];
    const float* pw   = (const float*)d_in[10];
    const float* pb   = (const float*)d_in[11];
    const float* W1   = (const float*)d_in[12];
    const float* b1   = (const float*)d_in[13];
    const float* W2   = (const float*)d_in[14];
    const float* b2   = (const float*)d_in[15];
    float* out = (float*)d_out;

    // Idempotent, not stream ops -> graph-capture safe; no static guards (rule).
    cudaFuncSetAttribute(scan2_kernel, cudaFuncAttributeMaxDynamicSharedMemorySize,
                         SCAN2_SMEM);
    cudaFuncSetAttribute(bgemm_nt<0>, cudaFuncAttributeMaxDynamicSharedMemorySize,
                         BG_SMEM);
    cudaFuncSetAttribute(bgemm_nt<1>, cudaFuncAttributeMaxDynamicSharedMemorySize,
                         BG_SMEM);

    dim3 gg(8, 64), bt(256);

    // split inputs to bf16 hi/lo
    cvt_kernel<<<8192, 256>>>(hs, 0, 0, 2097152);
    cvt_kernel<<<1024, 256>>>(wq, 1, 0,       262144);
    cvt_kernel<<<1024, 256>>>(wk, 1, 1048576, 262144);
    cvt_kernel<<<1024, 256>>>(wv, 1, 2097152, 262144);
    cvt_kernel<<<1024, 256>>>(wo, 1, 3145728, 262144);

    // QKV projections on tensor cores
    bgemm_nt<0><<<gg, bt, BG_SMEM>>>(0, nullptr);
    bgemm_nt<0><<<gg, bt, BG_SMEM>>>(1, nullptr);
    bgemm_nt<0><<<gg, bt, BG_SMEM>>>(2, nullptr);

    rope_kernel<<<16384, 256>>>();
    lr_kernel<<<8192, 256>>>(hs, lrw, lrb);

    // cluster-split TTT scan: 64 clusters x 2 CTAs
    scan2_kernel<<<128, 256, SCAN2_SMEM>>>(lti, lnw, lnb, W1, b1, W2, b2);

    // post-LN writes bf16 hi/lo directly (cvt fused)
    postln_kernel<<<8192, 256>>>(pw, pb);

    // output projection on tensor cores
    bgemm_nt<1><<<gg, bt, BG_SMEM>>>(3, out);
}